// round 8
// baseline (speedup 1.0000x reference)
#include <cuda_runtime.h>
#include <cuda_fp8.h>
#include <cstdint>
#include <math.h>

#define BATCH   4096
#define NLEAF   50000
#define DIM     256
#define CHUNKL  5556
#define NCHUNK  9
#define NTILES  44
#define EPSF    1e-7f
#define NSLOT   8
#define MCAND   (NCHUNK * NSLOT * 2)   // 144 candidates per row
#define MSHORT  32                      // exact re-rank shortlist
#define LDEPTH  5                       // ceil(144/32)

// smem: 2 stages of {Xq, Yq}, each mat 128 rows x 144B pitch (128B fp8 chunk)
#define PITCH    144
#define MATB     (128 * PITCH)          // 18432
#define STAGEB   (2 * MATB)             // 36864
#define OFF_SCL  (2 * STAGEB)           // 73728 (float4 per col, 128 cols)
#define DPITCH   132                    // dump pitch (floats), overlays stages
#define SMEM_TOTAL (OFF_SCL + 128 * 16) // 75776

__device__ float g_x2[BATCH];
__device__ float g_sx[BATCH];           // X row dequant scale
__device__ float g_y2[NLEAF];
__device__ float4 g_scl[NLEAF];         // (inv, y2*inv, sy, 0)
__device__ __align__(16) uint8_t g_Xq[(size_t)BATCH * DIM];
__device__ __align__(16) uint8_t g_Yq[(size_t)NLEAF * DIM];  // e4m3 of -2*inv*y
__device__ float g_cval[(size_t)NCHUNK * BATCH * NSLOT * 2];
__device__ int   g_cidx[(size_t)NCHUNK * BATCH * NSLOT * 2];

__device__ __forceinline__ uint32_t smem_to_u32(const void* p) {
    uint32_t a;
    asm("{ .reg .u64 t; cvta.to.shared.u64 t, %1; cvt.u32.u64 %0, t; }" : "=r"(a) : "l"(p));
    return a;
}
#define LDSM_X4(r, addr) \
    asm volatile("ldmatrix.sync.aligned.m8n8.x4.shared.b16 {%0,%1,%2,%3}, [%4];" \
        : "=r"((r)[0]), "=r"((r)[1]), "=r"((r)[2]), "=r"((r)[3]) : "r"(addr))
#define MMAF8(c, a, b0, b1) \
    asm volatile("mma.sync.aligned.m16n8k32.row.col.f32.e4m3.e4m3.f32 " \
        "{%0,%1,%2,%3},{%4,%5,%6,%7},{%8,%9},{%0,%1,%2,%3};" \
        : "+f"((c)[0]), "+f"((c)[1]), "+f"((c)[2]), "+f"((c)[3]) \
        : "r"((a)[0]), "r"((a)[1]), "r"((a)[2]), "r"((a)[3]), "r"(b0), "r"(b1))
#define CP_WAIT(n) asm volatile("cp.async.wait_group %0;" :: "n"(n) : "memory")

// ---------------- Kernel 1: norms + per-row e4m3 quantization -------------
// X rows: q(x / sx).  Y rows: q(-2*inv*y / sy), inv = 1/(1-y2).
// key = dot_q*sx*sy + x2*inv[col] + y2inv[col]: monotone hyperbolic rank key.
// FP8 error << top-32 shortlist gap; exact fp32 re-rank of 32 follows.
__global__ void prep_kernel(const float* __restrict__ X, const float* __restrict__ Y) {
    int warp = (blockIdx.x * blockDim.x + threadIdx.x) >> 5;
    int lane = threadIdx.x & 31;
    if (warp >= BATCH + NLEAF) return;
    bool isX = warp < BATCH;
    int row = isX ? warp : warp - BATCH;
    const float* src = (isX ? X : Y) + (size_t)row * DIM;
    float4 a = ((const float4*)src)[lane * 2];
    float4 b = ((const float4*)src)[lane * 2 + 1];
    float v[8] = {a.x, a.y, a.z, a.w, b.x, b.y, b.z, b.w};
    float s = 0.0f;
    #pragma unroll
    for (int i = 0; i < 8; i++) s += v[i] * v[i];
    #pragma unroll
    for (int o = 16; o; o >>= 1) s += __shfl_xor_sync(0xffffffffu, s, o);

    float w[8];
    float inv = 1.0f;
    if (isX) {
        #pragma unroll
        for (int i = 0; i < 8; i++) w[i] = v[i];
    } else {
        inv = 1.0f / (1.0f - s);
        float sc = -2.0f * inv;
        #pragma unroll
        for (int i = 0; i < 8; i++) w[i] = v[i] * sc;
    }
    float m = 0.0f;
    #pragma unroll
    for (int i = 0; i < 8; i++) m = fmaxf(m, fabsf(w[i]));
    #pragma unroll
    for (int o = 16; o; o >>= 1) m = fmaxf(m, __shfl_xor_sync(0xffffffffu, m, o));
    m = fmaxf(m, 1e-30f);
    float Kq = 448.0f / m;

    uint32_t p0 = 0, p1 = 0;
    #pragma unroll
    for (int i = 0; i < 4; i++) {
        uint32_t bb = (uint32_t)__nv_cvt_float_to_fp8(w[i] * Kq, __NV_SATFINITE, __NV_E4M3);
        p0 |= bb << (8 * i);
    }
    #pragma unroll
    for (int i = 0; i < 4; i++) {
        uint32_t bb = (uint32_t)__nv_cvt_float_to_fp8(w[4 + i] * Kq, __NV_SATFINITE, __NV_E4M3);
        p1 |= bb << (8 * i);
    }
    if (isX) {
        ((uint2*)(g_Xq + (size_t)row * DIM))[lane] = make_uint2(p0, p1);
        if (lane == 0) { g_x2[row] = s; g_sx[row] = m * (1.0f / 448.0f); }
    } else {
        ((uint2*)(g_Yq + (size_t)row * DIM))[lane] = make_uint2(p0, p1);
        if (lane == 0) {
            g_y2[row] = s;
            g_scl[row] = make_float4(inv, s * inv, m * (1.0f / 448.0f), 0.0f);
        }
    }
}

// cp.async one 128-byte k-chunk of Xq and Yq tiles into one smem stage.
__device__ __forceinline__ void issue_loads(uint32_t stg, int tid, int mrow0,
                                            int leaf0, int kc) {
    const int k0 = kc * 128;
    #pragma unroll
    for (int i = 0; i < 8; i++) {
        int u = tid + 256 * i;
        int mat = u >> 10;
        int rem = u & 1023;
        int row = rem >> 3;
        int col = rem & 7;
        uint32_t dst = stg + (uint32_t)mat * MATB + (uint32_t)row * PITCH
                     + (uint32_t)col * 16;
        const uint8_t* src;
        if (mat == 0) {
            src = g_Xq + (size_t)(mrow0 + row) * DIM + k0 + col * 16;
        } else {
            int leaf = leaf0 + row; if (leaf >= NLEAF) leaf = NLEAF - 1;
            src = g_Yq + (size_t)leaf * DIM + k0 + col * 16;
        }
        asm volatile("cp.async.cg.shared.global [%0], [%1], 16;"
                     :: "r"(dst), "l"(src) : "memory");
    }
    asm volatile("cp.async.commit_group;" ::: "memory");
}

// ---------------- Kernel 2: single-pass e4m3 mma.sync GEMM + fused top-8 --
// 256 threads = 8 warps (2m x 4n), warp tile 64x32, block tile 128x128, K=256.
__global__ void __launch_bounds__(256, 2) main_kernel() {
    extern __shared__ char smem[];
    const uint32_t sb = smem_to_u32(smem);
    const int tid = threadIdx.x, lane = tid & 31, w = tid >> 5;
    const int wm = w >> 2, wn = w & 3;
    const int mblk = blockIdx.x, chunk = blockIdx.y;
    const int mrow0 = mblk * 128;
    const int leaf_base = chunk * CHUNKL;
    int leaf_end = leaf_base + CHUNKL; if (leaf_end > NLEAF) leaf_end = NLEAF;

    // fragment address components (byte geometry identical to verified s8 path)
    const uint32_t aoff = (uint32_t)(wm * 64 + (lane & 15)) * PITCH
                        + ((lane >> 4) & 1) * 16;
    const uint32_t boff = (uint32_t)(wn * 32 + (lane & 7) + ((lane >> 4) & 1) * 8) * PITCH
                        + ((lane >> 3) & 1) * 16;

    // dump-phase row constants: 8 owned rows, fixed across tiles
    float x2r8[8], sxr8[8];
    {
        const int rbase = mrow0 + wm * 64 + (lane >> 2);
        #pragma unroll
        for (int mi = 0; mi < 4; mi++)
            #pragma unroll
            for (int h = 0; h < 2; h++) {
                int r = rbase + mi * 16 + h * 8;
                x2r8[mi * 2 + h] = g_x2[r];
                sxr8[mi * 2 + h] = g_sx[r];
            }
    }
    const uint32_t sSCL = sb + OFF_SCL;

    float tv[NSLOT]; int ti[NSLOT];
    #pragma unroll
    for (int q = 0; q < NSLOT; q++) { tv[q] = INFINITY; ti[q] = -1; }

    for (int t = 0; t < NTILES; t++) {
        const int leaf0 = leaf_base + t * 128;
        issue_loads(sb, tid, mrow0, leaf0, 0);
        // stage per-col (inv, y2inv, sy) for this tile
        if (tid < 128) {
            int leaf = leaf0 + tid; if (leaf >= NLEAF) leaf = NLEAF - 1;
            float4 sc = g_scl[leaf];
            asm volatile("st.shared.v4.f32 [%0], {%1,%2,%3,%4};"
                         :: "r"(sSCL + tid * 16), "f"(sc.x), "f"(sc.y), "f"(sc.z), "f"(sc.w)
                         : "memory");
        }

        float c[4][4][4];
        #pragma unroll
        for (int mi = 0; mi < 4; mi++)
            #pragma unroll
            for (int ni = 0; ni < 4; ni++)
                #pragma unroll
                for (int e = 0; e < 4; e++) c[mi][ni][e] = 0.0f;

        #pragma unroll
        for (int kc = 0; kc < 2; kc++) {
            const uint32_t stg = sb + (uint32_t)kc * STAGEB;
            if (kc == 0) {
                issue_loads(sb + STAGEB, tid, mrow0, leaf0, 1);
                CP_WAIT(1);
            } else {
                CP_WAIT(0);
            }
            __syncthreads();

            #pragma unroll
            for (int ks = 0; ks < 4; ks++) {
                uint32_t a[4][4], b[2][4];
                #pragma unroll
                for (int mi = 0; mi < 4; mi++)
                    LDSM_X4(a[mi], stg + (uint32_t)(mi * 16) * PITCH + ks * 32 + aoff);
                #pragma unroll
                for (int nb = 0; nb < 2; nb++)
                    LDSM_X4(b[nb], stg + MATB + (uint32_t)(nb * 16) * PITCH + ks * 32 + boff);
                #pragma unroll
                for (int mi = 0; mi < 4; mi++) {
                    #pragma unroll
                    for (int nb = 0; nb < 2; nb++) {
                        MMAF8(c[mi][2 * nb],     a[mi], b[nb][0], b[nb][1]);
                        MMAF8(c[mi][2 * nb + 1], a[mi], b[nb][2], b[nb][3]);
                    }
                }
            }
            __syncthreads();
        }

        // dump: apply scales + affine, write final keys (overlays dead stages)
        {
            const int r0 = wm * 64 + (lane >> 2);
            const int c0 = wn * 32 + 2 * (lane & 3);
            #pragma unroll
            for (int ni = 0; ni < 4; ni++) {
                int cA = c0 + ni * 8;
                float4 sA, sB;
                asm volatile("ld.shared.v4.f32 {%0,%1,%2,%3}, [%4];"
                             : "=f"(sA.x), "=f"(sA.y), "=f"(sA.z), "=f"(sA.w)
                             : "r"(sSCL + cA * 16));
                asm volatile("ld.shared.v4.f32 {%0,%1,%2,%3}, [%4];"
                             : "=f"(sB.x), "=f"(sB.y), "=f"(sB.z), "=f"(sB.w)
                             : "r"(sSCL + (cA + 1) * 16));
                #pragma unroll
                for (int mi = 0; mi < 4; mi++) {
                    float af0A = fmaf(x2r8[2*mi],   sA.x, sA.y);
                    float af0B = fmaf(x2r8[2*mi],   sB.x, sB.y);
                    float af1A = fmaf(x2r8[2*mi+1], sA.x, sA.y);
                    float af1B = fmaf(x2r8[2*mi+1], sB.x, sB.y);
                    float k0 = fmaf(c[mi][ni][0], sxr8[2*mi]   * sA.z, af0A);
                    float k1 = fmaf(c[mi][ni][1], sxr8[2*mi]   * sB.z, af0B);
                    float k2 = fmaf(c[mi][ni][2], sxr8[2*mi+1] * sA.z, af1A);
                    float k3 = fmaf(c[mi][ni][3], sxr8[2*mi+1] * sB.z, af1B);
                    uint32_t a0 = sb + (uint32_t)((r0 + mi * 16) * DPITCH + cA) * 4;
                    asm volatile("st.shared.v2.f32 [%0], {%1,%2};"
                                 :: "r"(a0), "f"(k0), "f"(k1) : "memory");
                    asm volatile("st.shared.v2.f32 [%0], {%1,%2};"
                                 :: "r"(a0 + 8 * DPITCH * 4), "f"(k2), "f"(k3) : "memory");
                }
            }
        }
        __syncthreads();

        // scan: thread owns (row = tid&127, half): top-8 over 64 key cols
        {
            const int half = tid >> 7;
            int nvalid = leaf_end - leaf0; if (nvalid > 128) nvalid = 128;
            const uint32_t rb = sb + (uint32_t)(tid & 127) * (DPITCH * 4) + half * 256;
            #pragma unroll 4
            for (int j4 = 0; j4 < 16; j4++) {
                float v0, v1, v2, v3;
                asm volatile("ld.shared.v4.f32 {%0,%1,%2,%3}, [%4];"
                             : "=f"(v0), "=f"(v1), "=f"(v2), "=f"(v3)
                             : "r"(rb + j4 * 16));
                float vv[4] = {v0, v1, v2, v3};
                #pragma unroll
                for (int e = 0; e < 4; e++) {
                    int col = half * 64 + j4 * 4 + e;
                    float key = vv[e];
                    if (col < nvalid && key < tv[NSLOT - 1]) {
                        tv[NSLOT - 1] = key; ti[NSLOT - 1] = leaf0 + col;
                        #pragma unroll
                        for (int q = NSLOT - 1; q > 0; q--) {
                            if (tv[q] < tv[q - 1]) {
                                float fv = tv[q]; tv[q] = tv[q - 1]; tv[q - 1] = fv;
                                int iv = ti[q]; ti[q] = ti[q - 1]; ti[q - 1] = iv;
                            }
                        }
                    }
                }
            }
        }
        __syncthreads();
    }

    const int grow_s = mrow0 + (tid & 127);
    const size_t cb = (((size_t)chunk * BATCH + grow_s) * 2 + (tid >> 7)) * NSLOT;
    #pragma unroll
    for (int q = 0; q < NSLOT; q++) { g_cval[cb + q] = tv[q]; g_cidx[cb + q] = ti[q]; }
}

// ---------------- Kernel 3: 144 cands -> approx top-32 -> exact re-rank ---
__global__ void merge_kernel(const float* __restrict__ X, const float* __restrict__ Y,
                             const int* __restrict__ ids, const float* __restrict__ thr_p,
                             float* __restrict__ out, int out_size) {
    const int lane = threadIdx.x & 31;
    const int row = blockIdx.x * 8 + (threadIdx.x >> 5);
    if (row >= BATCH) return;
    const unsigned FULL = 0xffffffffu;

    // per-lane sorted list over its <=5 strided candidates
    float lv[LDEPTH]; int li[LDEPTH];
    #pragma unroll
    for (int s = 0; s < LDEPTH; s++) { lv[s] = INFINITY; li[s] = 0x7fffffff; }
    for (int f = lane; f < MCAND; f += 32) {
        int ch = f >> 4, r = f & 15;
        size_t a = ((size_t)ch * BATCH + row) * 16 + r;
        float v = g_cval[a];
        int ix = g_cidx[a];
        if (ix < 0) continue;
        if (v < lv[LDEPTH - 1] || (v == lv[LDEPTH - 1] && ix < li[LDEPTH - 1])) {
            int p = LDEPTH - 1;
            while (p > 0 && (lv[p-1] > v || (lv[p-1] == v && li[p-1] > ix))) {
                lv[p] = lv[p-1]; li[p] = li[p-1]; p--;
            }
            lv[p] = v; li[p] = ix;
        }
    }

    // warp-wide selection of approx top-32 (lane r keeps r-th pick)
    int head = 0, seli = -1;
    for (int r = 0; r < MSHORT; r++) {
        float bv = (head < LDEPTH) ? lv[head] : INFINITY;
        int   bi = (head < LDEPTH) ? li[head] : 0x7fffffff;
        int   bl = lane;
        #pragma unroll
        for (int o = 16; o > 0; o >>= 1) {
            float ov = __shfl_down_sync(FULL, bv, o);
            int oi = __shfl_down_sync(FULL, bi, o);
            int ol = __shfl_down_sync(FULL, bl, o);
            if (ov < bv || (ov == bv && oi < bi)) { bv = ov; bi = oi; bl = ol; }
        }
        bi = __shfl_sync(FULL, bi, 0);
        bl = __shfl_sync(FULL, bl, 0);
        if (lane == r) seli = bi;
        if (lane == bl) head++;
    }

    // exact fp32 re-rank of the 32 candidates
    float x2 = g_x2[row];
    const float4* xr = (const float4*)(X + (size_t)row * DIM);
    float4 xa = xr[lane * 2], xb = xr[lane * 2 + 1];
    float my_dist = INFINITY;
    for (int cc = 0; cc < MSHORT; cc++) {
        int ci = __shfl_sync(FULL, seli, cc);
        float dist = INFINITY;
        if (ci >= 0 && ci < NLEAF) {
            const float4* yr = (const float4*)(Y + (size_t)ci * DIM);
            float4 ya = yr[lane * 2], yb = yr[lane * 2 + 1];
            float s = xa.x*ya.x + xa.y*ya.y + xa.z*ya.z + xa.w*ya.w
                    + xb.x*yb.x + xb.y*yb.y + xb.z*yb.z + xb.w*yb.w;
            #pragma unroll
            for (int o = 16; o > 0; o >>= 1) s += __shfl_down_sync(FULL, s, o);
            s = __shfl_sync(FULL, s, 0);
            float y2 = g_y2[ci];
            float sq    = fmaxf(x2 + y2 - 2.0f * s, 0.0f);
            float denom = fmaxf((1.0f - x2) * (1.0f - y2), EPSF);
            float arg   = fmaxf(1.0f + 2.0f * sq / denom, 1.0f + EPSF);
            dist = acoshf(arg);
        } else ci = -1;
        if (lane == cc) { my_dist = dist; seli = ci; }
    }

    // final: 5 argmin-by-(dist,idx) rounds with exclusion
    float d = my_dist;
    int   id = (seli < 0) ? 0x7fffffff : seli;
    float score = INFINITY;
    int outid[5];
    #pragma unroll
    for (int j = 0; j < 5; j++) {
        float bv = d; int bi = id;
        #pragma unroll
        for (int o = 16; o > 0; o >>= 1) {
            float ov = __shfl_down_sync(FULL, bv, o);
            int oi = __shfl_down_sync(FULL, bi, o);
            if (ov < bv || (ov == bv && oi < bi)) { bv = ov; bi = oi; }
        }
        bv = __shfl_sync(FULL, bv, 0);
        bi = __shfl_sync(FULL, bi, 0);
        if (j == 0) score = bv;
        outid[j] = bi;
        if (id == bi) d = INFINITY;   // exclude winner (idx unique)
    }

    if (lane == 0) {
        out[row] = score;
        if (out_size >= 2 * BATCH)
            out[BATCH + row] = (score > thr_p[0]) ? 1.0f : 0.0f;
        if (out_size >= 7 * BATCH) {
            #pragma unroll
            for (int j = 0; j < 5; j++) {
                int ci = outid[j];
                out[2 * BATCH + (size_t)row * 5 + j] =
                    (float)((ci >= 0 && ci < NLEAF) ? ids[ci] : 0);
            }
        }
    }
}

// ---------------------------------------------------------------------------
extern "C" void kernel_launch(void* const* d_in, const int* in_sizes, int n_in,
                              void* d_out, int out_size) {
    const float* X   = (const float*)d_in[0];
    const float* Y   = (const float*)d_in[1];
    const int*   ids = (const int*)d_in[2];
    const float* thr = (const float*)d_in[3];
    float* out = (float*)d_out;

    cudaFuncSetAttribute(main_kernel, cudaFuncAttributeMaxDynamicSharedMemorySize,
                         SMEM_TOTAL);

    int prep_warps = BATCH + NLEAF;
    prep_kernel<<<(prep_warps + 7) / 8, 256>>>(X, Y);

    main_kernel<<<dim3(BATCH / 128, NCHUNK), 256, SMEM_TOTAL>>>();

    merge_kernel<<<BATCH / 8, 256>>>(X, Y, ids, thr, out, out_size);
}